// round 10
// baseline (speedup 1.0000x reference)
#include <cuda_runtime.h>
#include <cuda_fp16.h>
#include <cstdint>

#define D 64
#define MAXN 100000
#define MAXE 1600000
#define SCAN_BLK 1024

// Scratch (device globals — no allocation allowed; zero-initialized at load,
// and every kernel sequence restores the zero-invariants it consumes)
__device__ float g_agg[MAXN * D];      // agg result; later reused as t2
__device__ float g_t1[MAXN * D];       // output of first Linear
__device__ float g_stats[256];         // sum1[64], sq1[64], sum2[64], sq2[64]
__device__ uint2 g_xh[MAXN * 16];      // x staged as fp16 (64 halfs/row = 128B)
__device__ int   g_cnt[MAXN + SCAN_BLK];  // degree hist (zeroed by k_scan after use)
__device__ int   g_start[MAXN + 1];
__device__ int   g_cursor[MAXN];
__device__ int   g_srcs[MAXE];
__device__ int   g_bsum[SCAN_BLK];
__device__ int   g_ctr;                // grid-barrier counters (self-resetting)
__device__ int   g_ctr2;

// ---------------------------------------------------------------------------
// K_prep: stage x as fp16 + degree histogram + zero stats.
// ---------------------------------------------------------------------------
__global__ __launch_bounds__(256) void k_prep(const float* __restrict__ x,
                                              const int* __restrict__ ei,
                                              int N, int E) {
    int i = blockIdx.x * 256 + threadIdx.x;
    if (i < 256) g_stats[i] = 0.f;
    if (i == 0) g_start[N] = E;
    if (i < E) atomicAdd(&g_cnt[ei[E + i]], 1);
    int n4 = N * 16;
    if (i >= n4) return;
    float4 v = ((const float4*)x)[i];
    __half2 h0 = __floats2half2_rn(v.x, v.y);
    __half2 h1 = __floats2half2_rn(v.z, v.w);
    uint2 u;
    u.x = *(unsigned*)&h0;
    u.y = *(unsigned*)&h1;
    g_xh[i] = u;
}

__device__ __forceinline__ int block_scan_1024(int v, int* warpsum, int* total) {
    int lane = threadIdx.x & 31, wid = threadIdx.x >> 5;
    int inc = v;
    #pragma unroll
    for (int o = 1; o < 32; o <<= 1) {
        int u = __shfl_up_sync(0xFFFFFFFFu, inc, o);
        if (lane >= o) inc += u;
    }
    if (lane == 31) warpsum[wid] = inc;
    __syncthreads();
    if (wid == 0) {
        int w = warpsum[lane];
        #pragma unroll
        for (int o = 1; o < 32; o <<= 1) {
            int u = __shfl_up_sync(0xFFFFFFFFu, w, o);
            if (lane >= o) w += u;
        }
        warpsum[lane] = w;
    }
    __syncthreads();
    int base = (wid > 0) ? warpsum[wid - 1] : 0;
    *total = warpsum[31];
    return inc + base;
}

// ---------------------------------------------------------------------------
// K_scan: single-kernel exclusive scan (grid resident => sw barrier safe).
// ---------------------------------------------------------------------------
__global__ __launch_bounds__(SCAN_BLK) void k_scan(int N) {
    __shared__ int warpsum[32];
    __shared__ int s_base;
    int gi = blockIdx.x * SCAN_BLK + threadIdx.x;
    int v = (gi < N) ? g_cnt[gi] : 0;
    if (gi < N) g_cnt[gi] = 0;                 // restore zero-invariant
    int total;
    int incl = block_scan_1024(v, warpsum, &total);

    if (threadIdx.x == 0) {
        g_bsum[blockIdx.x] = total;
        __threadfence();
        atomicAdd(&g_ctr, 1);
        while (atomicAdd(&g_ctr, 0) < (int)gridDim.x) {}
        __threadfence();
    }
    __syncthreads();

    if (threadIdx.x < 32) {
        int base = 0;
        for (int j = threadIdx.x; j < (int)blockIdx.x; j += 32) base += g_bsum[j];
        #pragma unroll
        for (int o = 16; o >= 1; o >>= 1) base += __shfl_down_sync(0xFFFFFFFFu, base, o);
        if (threadIdx.x == 0) s_base = base;
    }
    __syncthreads();

    if (gi < N) {
        int st = s_base + incl - v;
        g_start[gi] = st;
        g_cursor[gi] = st;
    }

    if (threadIdx.x == 0) {
        int done = atomicAdd(&g_ctr2, 1);
        if (done == (int)gridDim.x - 1) { g_ctr = 0; g_ctr2 = 0; }
    }
}

__global__ __launch_bounds__(256) void k_fill(const int* __restrict__ ei, int E) {
    int e = blockIdx.x * 256 + threadIdx.x;
    if (e >= E) return;
    int src = ei[e];
    int dst = ei[E + e];
    int pos = atomicAdd(&g_cursor[dst], 1);
    g_srcs[pos] = src;
}

// ---------------------------------------------------------------------------
// K_agg: (1+eps)*x[i](fp32) + neighbor sum. 8 threads/node, uint4 gathers,
// fp16 HADD2 accumulation flushed to fp32 every 8 edges (instruction diet:
// 4 HADD2/edge instead of 4 CVT + 8 FADD).
// ---------------------------------------------------------------------------
__global__ __launch_bounds__(256) void k_agg(const float* __restrict__ x,
                                             const float* __restrict__ epsp,
                                             float* __restrict__ agg, int N) {
    int tid = threadIdx.x;
    int i = blockIdx.x * 32 + (tid >> 3);
    int q = tid & 7;
    if (i >= N) return;
    float s = 1.0f + epsp[0];
    float4 x0 = ((const float4*)x)[(size_t)i * 16 + q * 2];
    float4 x1 = ((const float4*)x)[(size_t)i * 16 + q * 2 + 1];
    float4 acc0 = make_float4(x0.x * s, x0.y * s, x0.z * s, x0.w * s);
    float4 acc1 = make_float4(x1.x * s, x1.y * s, x1.z * s, x1.w * s);
    int j = g_start[i];
    int je = g_start[i + 1];
    const uint4* xh4 = (const uint4*)g_xh;
    const __half2 hz = __floats2half2_rn(0.f, 0.f);
    while (j < je) {
        int jend = j + 8;
        if (jend > je) jend = je;
        __half2 h0 = hz, h1 = hz, h2 = hz, h3 = hz;
        for (; j < jend; j++) {
            uint4 u = xh4[(size_t)g_srcs[j] * 8 + q];
            h0 = __hadd2(h0, *(__half2*)&u.x);
            h1 = __hadd2(h1, *(__half2*)&u.y);
            h2 = __hadd2(h2, *(__half2*)&u.z);
            h3 = __hadd2(h3, *(__half2*)&u.w);
        }
        float2 f0 = __half22float2(h0);
        float2 f1 = __half22float2(h1);
        float2 f2 = __half22float2(h2);
        float2 f3 = __half22float2(h3);
        acc0.x += f0.x; acc0.y += f0.y; acc0.z += f1.x; acc0.w += f1.y;
        acc1.x += f2.x; acc1.y += f2.y; acc1.z += f3.x; acc1.w += f3.y;
    }
    ((float4*)agg)[(size_t)i * 16 + q * 2] = acc0;
    ((float4*)agg)[(size_t)i * 16 + q * 2 + 1] = acc1;
}

// ---------------------------------------------------------------------------
// fp16 HMMA GEMM (m16n8k16, fp32 accum) + fused BN stats. (verified)
// ---------------------------------------------------------------------------
#define MMA_F16(c, a0, a1, a2, a3, b0, b1)                                    \
    asm volatile(                                                             \
        "mma.sync.aligned.m16n8k16.row.col.f32.f16.f16.f32 "                  \
        "{%0,%1,%2,%3}, {%4,%5,%6,%7}, {%8,%9}, {%0,%1,%2,%3};"               \
        : "+f"(c[0]), "+f"(c[1]), "+f"(c[2]), "+f"(c[3])                      \
        : "r"(a0), "r"(a1), "r"(a2), "r"(a3), "r"(b0), "r"(b1))

__global__ __launch_bounds__(256) void k_gemm_hmma(
    const float* __restrict__ in, const float* __restrict__ W,
    const float* __restrict__ b, float* __restrict__ out,
    float* __restrict__ statsOut,
    const float* __restrict__ statsIn,
    const float* __restrict__ gamma, const float* __restrict__ beta,
    int N, int applyBNin)
{
    __shared__ unsigned Xs[64 * 68];
    __shared__ unsigned Wsm[32 * 72];
    __shared__ float Bs[64], SC[64], SH[64];
    __shared__ float redS[8][32], redQ[8][32];

    const int tid = threadIdx.x;
    const int row0 = blockIdx.x * 64;

    if (tid < 64) {
        Bs[tid] = b[tid];
        if (applyBNin) {
            float invN = 1.0f / (float)N;
            float mean = statsIn[tid] * invN;
            float var  = statsIn[64 + tid] * invN - mean * mean;
            float sc = gamma[tid] * rsqrtf(var + 1e-5f);
            SC[tid] = sc;
            SH[tid] = beta[tid] - mean * sc;
        }
    }
    __syncthreads();

    #pragma unroll
    for (int it = 0; it < 8; it++) {
        int idx = tid + it * 256;
        int k2 = idx >> 6, n = idx & 63;
        float w0 = W[(2 * k2) * 64 + n];
        float w1 = W[(2 * k2 + 1) * 64 + n];
        __half2 h = __floats2half2_rn(w0, w1);
        Wsm[k2 * 72 + n] = *(unsigned*)&h;
    }
    #pragma unroll
    for (int it = 0; it < 8; it++) {
        int idx = tid + it * 256;
        int row = idx >> 5, k2 = idx & 31;
        int gr = row0 + row;
        float2 v = make_float2(0.f, 0.f);
        if (gr < N) v = ((const float2*)in)[(size_t)gr * 32 + k2];
        if (applyBNin) {
            int c = k2 * 2;
            v.x = fmaxf(fmaf(v.x, SC[c], SH[c]), 0.f);
            v.y = fmaxf(fmaf(v.y, SC[c + 1], SH[c + 1]), 0.f);
        }
        __half2 h = __floats2half2_rn(v.x, v.y);
        Xs[row * 68 + k2] = *(unsigned*)&h;
    }
    __syncthreads();

    const int w = tid >> 5, lane = tid & 31;
    const int ms = w & 3, nh = w >> 2;
    const int g = lane >> 2, t4 = lane & 3;
    const int mbase = ms * 16;
    const int nbase = nh * 32;

    float c_[4][4];
    #pragma unroll
    for (int nt = 0; nt < 4; nt++) {
        int col0 = nbase + nt * 8 + 2 * t4;
        c_[nt][0] = Bs[col0]; c_[nt][1] = Bs[col0 + 1];
        c_[nt][2] = Bs[col0]; c_[nt][3] = Bs[col0 + 1];
    }

    #pragma unroll
    for (int kk = 0; kk < 4; kk++) {
        int kb = kk * 8;
        unsigned A0 = Xs[(mbase + g) * 68 + kb + t4];
        unsigned A1 = Xs[(mbase + g + 8) * 68 + kb + t4];
        unsigned A2 = Xs[(mbase + g) * 68 + kb + t4 + 4];
        unsigned A3 = Xs[(mbase + g + 8) * 68 + kb + t4 + 4];
        #pragma unroll
        for (int nt = 0; nt < 4; nt++) {
            int n = nbase + nt * 8 + g;
            unsigned B0 = Wsm[(kb + t4) * 72 + n];
            unsigned B1 = Wsm[(kb + t4 + 4) * 72 + n];
            MMA_F16(c_[nt], A0, A1, A2, A3, B0, B1);
        }
    }

    int rg0 = row0 + mbase + g;
    int rg8 = rg0 + 8;
    #pragma unroll
    for (int nt = 0; nt < 4; nt++) {
        int col0 = nbase + nt * 8 + 2 * t4;
        float s0 = 0.f, s1 = 0.f, q0 = 0.f, q1 = 0.f;
        if (rg0 < N) {
            *(float2*)&out[(size_t)rg0 * 64 + col0] = make_float2(c_[nt][0], c_[nt][1]);
            s0 += c_[nt][0]; s1 += c_[nt][1];
            q0 += c_[nt][0] * c_[nt][0]; q1 += c_[nt][1] * c_[nt][1];
        }
        if (rg8 < N) {
            *(float2*)&out[(size_t)rg8 * 64 + col0] = make_float2(c_[nt][2], c_[nt][3]);
            s0 += c_[nt][2]; s1 += c_[nt][3];
            q0 += c_[nt][2] * c_[nt][2]; q1 += c_[nt][3] * c_[nt][3];
        }
        #pragma unroll
        for (int o = 16; o >= 4; o >>= 1) {
            s0 += __shfl_down_sync(0xFFFFFFFFu, s0, o);
            s1 += __shfl_down_sync(0xFFFFFFFFu, s1, o);
            q0 += __shfl_down_sync(0xFFFFFFFFu, q0, o);
            q1 += __shfl_down_sync(0xFFFFFFFFu, q1, o);
        }
        if (lane < 4) {
            redS[w][nt * 8 + 2 * t4] = s0;
            redS[w][nt * 8 + 2 * t4 + 1] = s1;
            redQ[w][nt * 8 + 2 * t4] = q0;
            redQ[w][nt * 8 + 2 * t4 + 1] = q1;
        }
    }
    __syncthreads();
    if (tid < 64) {
        int hh = tid >> 5, lc = tid & 31;
        float s = redS[hh * 4 + 0][lc] + redS[hh * 4 + 1][lc]
                + redS[hh * 4 + 2][lc] + redS[hh * 4 + 3][lc];
        float q = redQ[hh * 4 + 0][lc] + redQ[hh * 4 + 1][lc]
                + redQ[hh * 4 + 2][lc] + redQ[hh * 4 + 3][lc];
        atomicAdd(&statsOut[tid], s);
        atomicAdd(&statsOut[64 + tid], q);
    }
}

// ---------------------------------------------------------------------------
// K_final: out = x + relu(BN(t2))
// ---------------------------------------------------------------------------
__global__ __launch_bounds__(256) void k_final(const float* __restrict__ x,
                                               const float* __restrict__ t2,
                                               const float* __restrict__ statsIn,
                                               const float* __restrict__ gamma,
                                               const float* __restrict__ beta,
                                               float* __restrict__ out, int N) {
    __shared__ float SC[64];
    __shared__ float SH[64];
    int tid = threadIdx.x;
    if (tid < 64) {
        float invN = 1.0f / (float)N;
        float mean = statsIn[tid] * invN;
        float var  = statsIn[64 + tid] * invN - mean * mean;
        float sc = gamma[tid] * rsqrtf(var + 1e-5f);
        SC[tid] = sc;
        SH[tid] = beta[tid] - mean * sc;
    }
    __syncthreads();
    int n4 = N * 16;
    for (int i = blockIdx.x * 256 + tid; i < n4; i += gridDim.x * 256) {
        int c = (i & 15) * 4;
        float4 v = ((const float4*)t2)[i];
        float4 xv = ((const float4*)x)[i];
        float4 o;
        o.x = xv.x + fmaxf(fmaf(v.x, SC[c + 0], SH[c + 0]), 0.f);
        o.y = xv.y + fmaxf(fmaf(v.y, SC[c + 1], SH[c + 1]), 0.f);
        o.z = xv.z + fmaxf(fmaf(v.z, SC[c + 2], SH[c + 2]), 0.f);
        o.w = xv.w + fmaxf(fmaf(v.w, SC[c + 3], SH[c + 3]), 0.f);
        ((float4*)out)[i] = o;
    }
}

// ---------------------------------------------------------------------------
extern "C" void kernel_launch(void* const* d_in, const int* in_sizes, int n_in,
                              void* d_out, int out_size) {
    const float* x    = (const float*)d_in[0];
    const int*   ei   = (const int*)d_in[1];
    const float* eps  = (const float*)d_in[2];
    const float* W1   = (const float*)d_in[3];
    const float* b1   = (const float*)d_in[4];
    const float* g1   = (const float*)d_in[5];
    const float* beta1= (const float*)d_in[6];
    const float* W2   = (const float*)d_in[7];
    const float* b2   = (const float*)d_in[8];
    const float* gh   = (const float*)d_in[9];
    const float* betah= (const float*)d_in[10];
    float* out = (float*)d_out;

    int N = in_sizes[0] / D;
    int E = in_sizes[1] / 2;
    if (N > MAXN) N = MAXN;
    if (E > MAXE) E = MAXE;

    float* agg;   cudaGetSymbolAddress((void**)&agg, g_agg);
    float* t1;    cudaGetSymbolAddress((void**)&t1, g_t1);
    float* stats; cudaGetSymbolAddress((void**)&stats, g_stats);

    int prepThreads = (N * 16 > E) ? N * 16 : E;
    int nScanBlocks = (N + SCAN_BLK - 1) / SCAN_BLK;   // 98 <= 148: resident

    k_prep<<<(prepThreads + 255) / 256, 256>>>(x, ei, N, E);
    k_scan<<<nScanBlocks, SCAN_BLK>>>(N);
    k_fill<<<(E + 255) / 256, 256>>>(ei, E);
    k_agg<<<(N + 31) / 32, 256>>>(x, eps, agg, N);

    int gemmBlocks = (N + 63) / 64;
    k_gemm_hmma<<<gemmBlocks, 256>>>(agg, W1, b1, t1, stats,
                                     nullptr, nullptr, nullptr, N, 0);
    k_gemm_hmma<<<gemmBlocks, 256>>>(t1, W2, b2, agg, stats + 128,
                                     stats, g1, beta1, N, 1);

    k_final<<<(N * 16 + 255) / 256, 256>>>(x, agg, stats + 128, gh, betah, out, N);
}